// round 13
// baseline (speedup 1.0000x reference)
#include <cuda_runtime.h>
#include <math.h>

#define N_IMG   512
#define N_ANG   25
#define N_DET   512
#define N_SAMP  1024
#define N_RAYS  (N_ANG * N_DET)
#define TB      514              // bordered coords: gq = g0+1, fq = f0+1, in [0, 513]
#define TBH     257              // g pair-row count

#define SRC_DIST 512.0f
#define DET_DIST 512.0f
#define DET_SPACING 3.0f

// Row-pair interleaved differential quad tables:
// slot(gq,fq) = ((gq>>1)*TB + fq)*2 + (gq&1)  -> 128B line = 4(f) x 2(g) footprint.
// Payload: .x=v00 .y=v01-v00 .z=v10-v00 .w=v11-v10-v01+v00 ; bilinear = .x+wf*.y+wg*(.z+wf*.w)
//  g_quadB : g = image row, f = image col ; g_quadBT: g = col, f = row (v(g,f)=img[f][g])
__device__ float4 g_quadB [TBH * TB * 2];
__device__ float4 g_quadBT[TBH * TB * 2];

__device__ __forceinline__ float4 diffquad(float a, float b, float c, float d) {
    return make_float4(a, b - a, c - a, (d - c) - (b - a));
}

// Tile: 32 g x 32 f quad entries per block; smem = 33x33 source patch.
// Lane->slot mapping is identity-contiguous: each STG.128 writes 32
// consecutive slots = 512B fully coalesced (R12 win).
__global__ __launch_bounds__(256)
void prep_kernel(const float* __restrict__ img) {
    __shared__ float sm[33][33];
    int tx = threadIdx.x;              // 0..31
    int ty = threadIdx.y;              // 0..7
    int fbase = blockIdx.x * 32;       // fq tile base
    int gbase = blockIdx.y * 32;       // gq tile base (16 pair-rows)
    int z = blockIdx.z;

    int gs = gbase - 1, fs = fbase - 1;
    bool interior = (gs >= 0) & (fs >= 0) & (gs + 32 < N_IMG) & (fs + 32 < N_IMG);

    if (interior) {
        if (z == 0) {
            #pragma unroll
            for (int a = ty; a < 33; a += 8) {
                const float* rp = img + (gs + a) * N_IMG + fs;
                sm[a][tx] = rp[tx];
                if (tx == 0) sm[a][32] = rp[32];
            }
        } else {
            #pragma unroll
            for (int b = ty; b < 33; b += 8) {
                const float* rp = img + (fs + b) * N_IMG + gs;
                sm[tx][b] = rp[tx];
                if (tx == 0) sm[32][b] = rp[32];
            }
        }
    } else {
        if (z == 0) {
            for (int a = ty; a < 33; a += 8) {
                int r = gs + a;
                bool rok = (r >= 0) & (r < N_IMG);
                for (int b = tx; b < 33; b += 32) {
                    int c = fs + b;
                    sm[a][b] = (rok && c >= 0 && c < N_IMG) ? img[r * N_IMG + c] : 0.0f;
                }
            }
        } else {
            for (int b = ty; b < 33; b += 8) {
                int r = fs + b;
                bool rok = (r >= 0) & (r < N_IMG);
                for (int a = tx; a < 33; a += 32) {
                    int c = gs + a;
                    sm[a][b] = (rok && c >= 0 && c < N_IMG) ? img[r * N_IMG + c] : 0.0f;
                }
            }
        }
    }
    __syncthreads();

    float4* __restrict__ dst = z ? g_quadBT : g_quadB;

    int p  = tx & 1;                 // g parity handled by this lane
    int fl = tx >> 1;                // f sub-index (0..15)
    int gpair_base = blockIdx.y * 16;

    #pragma unroll
    for (int it = ty; it < 32; it += 8) {
        int pl = it >> 1;            // pair-row 0..15
        int h  = it & 1;             // f half 0..1
        int ff = h * 16 + fl;        // local f 0..31
        int gg = 2 * pl + p;         // local g 0..31
        int fq = fbase + ff;
        int gq = gbase + gg;
        if (fq < TB && gq < TB) {
            float4 q = diffquad(sm[gg][ff], sm[gg][ff + 1],
                                sm[gg + 1][ff], sm[gg + 1][ff + 1]);
            dst[(((gpair_base + pl) * TB) + fq) * 2 + p] = q;
        }
    }
}

// shrink [u0,u1] so that p + u*v stays within [lo, hi]
__device__ __forceinline__ void clip_axis(float p, float v, float lo, float hi,
                                          float& u0, float& u1) {
    if (fabsf(v) < 1e-12f) {
        if (p < lo || p > hi) { u0 = 1e30f; u1 = -1e30f; }
    } else {
        float inv = __fdividef(1.0f, v);
        float a = (lo - p) * inv;
        float b = (hi - p) * inv;
        float mn = fminf(a, b), mx = fmaxf(a, b);
        u0 = fmaxf(u0, mn);
        u1 = fminf(u1, mx);
    }
}

// Single-wave, balanced: 6400 warps (800 blocks). Warp gw handles detectors
// dh and dh+256 of angle a (dh = gw & 255, a = gw >> 8). Central detectors
// (long chords) pair with edge detectors (short chords) -> near-uniform
// per-warp work, and 800 blocks fit in ONE wave (capacity 1184).
__global__ __launch_bounds__(256)
void fanbeam_kernel(float* __restrict__ out) {
    int w    = threadIdx.x >> 5;
    int lane = threadIdx.x & 31;
    int gw   = blockIdx.x * 8 + w;     // 0..6399

    int a  = gw >> 8;                  // angle
    int dh = gw & 255;                 // detector base (pairs with dh+256)

    float beta = (float)a * (2.0f * 3.14159265358979323846f / (float)N_ANG);
    float s, c;
    sincosf(beta, &s, &c);

    float sx = -SRC_DIST * s;
    float sy =  SRC_DIST * c;

    const float half  = (float)(N_IMG - 1) * 0.5f;   // 255.5
    const float inv_s = 1.0f / (float)N_SAMP;
    float cA = sx + half;          // col(u) = cA + u*dx
    float rA = half - sy;          // row(u) = rA - u*dy

    // ---- angle-level setup done; wait for prep_kernel's tables (PDL) ----
#if __CUDA_ARCH__ >= 900
    cudaGridDependencySynchronize();
#endif

    #pragma unroll
    for (int r = 0; r < 2; ++r) {
        int d = dh + (r << 8);

        float t  = ((float)d - (float)(N_DET - 1) * 0.5f) * DET_SPACING;
        float dx = t * c + DET_DIST * s - sx;
        float dy = t * s - DET_DIST * c - sy;
        float seg = sqrtf(dx * dx + dy * dy);

        float dxs = dx * inv_s;
        float dys = -dy * inv_s;
        float cA0 = fmaf(0.5f, dxs, cA);
        float rA0 = fmaf(0.5f, dys, rA);

        // orientation: fast axis = larger per-sample step; +1 shift to table coords
        bool swp = fabsf(dys) > fabsf(dxs);
        float fA0 = (swp ? rA0 : cA0) + 1.0f;
        float fds = swp ? dys : dxs;
        float gA0 = (swp ? cA0 : rA0) + 1.0f;
        float gds = swp ? dxs : dys;

        // clip coords to [-0.998, 512] -> floor in [-1, 512]
        float u0 = 0.0f, u1 = 1.0f;
        clip_axis(cA,  dx, -0.998f, 512.0f, u0, u1);
        clip_axis(rA, -dy, -0.998f, 512.0f, u0, u1);

        int s0 = max(0,          (int)ceilf (u0 * (float)N_SAMP - 0.5f));
        int s1 = min(N_SAMP - 1, (int)floorf(u1 * (float)N_SAMP - 0.5f));

        const float4* __restrict__ tab = swp ? g_quadBT : g_quadB;

        float acc = 0.0f;
        if (u0 <= u1) {
            #pragma unroll 4
            for (int i = s0 + lane; i <= s1; i += 32) {
                float fi = (float)i;
                float fp = fmaf(fi, fds, fA0);   // table coords (>= 0)
                float gp = fmaf(fi, gds, gA0);
                float fqf = floorf(fp);
                float gqf = floorf(gp);
                float wf = fp - fqf;
                float wg = gp - gqf;
                int fq = (int)fqf;
                int gq = (int)gqf;
                int slot = ((gq >> 1) * TB + fq) * 2 + (gq & 1);
                float4 q = __ldg(tab + slot);
                float u1v = fmaf(wf, q.y, q.x);
                float u2v = fmaf(wf, q.w, q.z);
                acc      += fmaf(wg, u2v, u1v);
            }
        }

        #pragma unroll
        for (int o = 16; o > 0; o >>= 1)
            acc += __shfl_down_sync(0xffffffffu, acc, o);

        if (lane == 0)
            out[a * N_DET + d] = acc * seg * inv_s;
    }
}

extern "C" void kernel_launch(void* const* d_in, const int* in_sizes, int n_in,
                              void* d_out, int out_size) {
    (void)in_sizes; (void)n_in; (void)out_size;
    const float* img = (const float*)d_in[0];
    float* out = (float*)d_out;

    dim3 tb(32, 8);
    dim3 tg(17, 17, 2);
    prep_kernel<<<tg, tb>>>(img);

    cudaLaunchConfig_t cfg = {};
    cfg.gridDim  = dim3(N_RAYS / 16, 1, 1);   // 800 blocks, 2 rays per warp
    cfg.blockDim = dim3(256, 1, 1);
    cfg.dynamicSmemBytes = 0;
    cudaLaunchAttribute attr[1];
    attr[0].id = cudaLaunchAttributeProgrammaticStreamSerialization;
    attr[0].val.programmaticStreamSerializationAllowed = 1;
    cfg.attrs = attr;
    cfg.numAttrs = 1;
    cudaLaunchKernelEx(&cfg, fanbeam_kernel, out);
}